// round 13
// baseline (speedup 1.0000x reference)
#include <cuda_runtime.h>
#include <float.h>

#define VOCAB 8000
#define C 256
#define P 8
#define BB 16
#define LL 2048
#define T 32                  // positions per block tile
#define ROWS (T + 2*P)        // 48 window rows, all register-resident
#define THREADS 256

__device__ float W_g[BB * LL * 16];   // gathered edge weights, [b*LL+l][16]
__device__ float NN_g[BB * LL];       // gathered node weights

__device__ __forceinline__ void cp_async16(void* smem, const void* gptr) {
    unsigned s = (unsigned)__cvta_generic_to_shared(smem);
    asm volatile("cp.async.ca.shared.global [%0], [%1], 16;" :: "r"(s), "l"(gptr));
}

__global__ void gnn_zero_out(float* out) {
    out[blockIdx.x * blockDim.x + threadIdx.x] = 0.0f;
}

// ---- kernel 1: saturating random gather -> coalesced scratch ----
__global__ __launch_bounds__(THREADS)
void gnn_gather(const int* __restrict__ ids,
                const float* __restrict__ ew,
                const float* __restrict__ nw)
{
    __shared__ int NX_s[ROWS];
    const int b  = blockIdx.y;
    const int l0 = blockIdx.x * T;
    const int* idrow = ids + b * LL;
    const int tid = threadIdx.x;

    if (tid < ROWS) {
        int p = l0 - P + tid;
        NX_s[tid] = (p >= 0 && p < LL) ? idrow[p] : 0;   // emb row 0 is all-zero
    }
    __syncthreads();

    // 2 independent random loads per thread (MLP=2); ~8 blocks/SM -> one wave,
    // DRAM-sector-throughput bound.
    int e0 = tid, e1 = tid + THREADS;
    int t0 = e0 >> 4, j0 = e0 & 15, k0 = j0 + (j0 >= P);
    int t1 = e1 >> 4, j1 = e1 & 15, k1 = j1 + (j1 >= P);
    // nx==0 -> emb row 0 all-zero -> product 0 regardless of weight value
    float w0 = ew[(size_t)NX_s[t0 + P] * VOCAB + NX_s[t0 + k0]];
    float w1 = ew[(size_t)NX_s[t1 + P] * VOCAB + NX_s[t1 + k1]];
    float nnv = (tid < T) ? nw[NX_s[tid + P]] : 0.f;

    size_t base = ((size_t)b * LL + l0) * 16;
    W_g[base + e0] = w0;
    W_g[base + e1] = w1;
    if (tid < T) NN_g[(size_t)b * LL + l0 + tid] = nnv;
}

// ---- kernel 2: compute, full-register window, no random loads ----
__global__ __launch_bounds__(THREADS, 3)
void gnn_kernel(const int* __restrict__ ids,
                const float* __restrict__ emb,
                float* __restrict__ out)
{
    __shared__ __align__(16) float W_s[T * 16];
    __shared__ __align__(16) float NN_s[T];
    __shared__ int NX_s[ROWS];

    const int b  = blockIdx.y;
    const int l0 = blockIdx.x * T;
    const int* idrow = ids + b * LL;
    const int tid = threadIdx.x;
    const int ct  = tid;                          // this thread's channel

    if (tid < ROWS) {
        int p = l0 - P + tid;
        NX_s[tid] = (p >= 0 && p < LL) ? idrow[p] : 0;
    }
    __syncthreads();

    // coalesced cp.async of this block's W tile (2KB) + NN (128B) from scratch
    if (tid < 128)
        cp_async16(&W_s[tid * 4], W_g + ((size_t)b * LL + l0) * 16 + tid * 4);
    else if (tid < 136)
        cp_async16(&NN_s[(tid - 128) * 4], NN_g + (size_t)b * LL + l0 + (tid - 128) * 4);
    asm volatile("cp.async.commit_group;" ::: "memory");

    // full-register window: 48 rows, MLP=48, compile-time indexed (no sliding)
    float win[ROWS];
    #pragma unroll
    for (int r = 0; r < ROWS; r++)
        win[r] = emb[(size_t)NX_s[r] * C + ct];

    asm volatile("cp.async.wait_group 0;" ::: "memory");
    __syncthreads();

    float acc = 0.f;
    float4 wa = ((const float4*)W_s)[0];
    float4 wb = ((const float4*)W_s)[1];
    float nn  = NN_s[0];

    #pragma unroll
    for (int tt = 0; tt < T; tt++) {
        // wc/wd loaded now, consumed >=16 instrs later (LDS latency hidden)
        const float4* wvt = (const float4*)(W_s + tt * 16);
        float4 wc = wvt[2], wd = wvt[3];

        float m0 = win[tt]     * wa.x;            // j=0
        float m1 = win[tt + 1] * wa.y;            // j=1
        #define STEP(j, wreg, m) m = fmaxf(m, win[tt + (j) + ((j) >= 8)] * (wreg));
        STEP(2,  wa.z, m0) STEP(3,  wa.w, m1)
        STEP(4,  wb.x, m0) STEP(5,  wb.y, m1) STEP(6,  wb.z, m0) STEP(7,  wb.w, m1)
        STEP(8,  wc.x, m0) STEP(9,  wc.y, m1) STEP(10, wc.z, m0) STEP(11, wc.w, m1)
        STEP(12, wd.x, m0) STEP(13, wd.y, m1) STEP(14, wd.z, m0) STEP(15, wd.w, m1)
        #undef STEP
        float m = fmaxf(m0, m1);

        float rn = win[tt + 8];
        acc += fmaf(nn, rn - m, m);               // (1-nn)*m + nn*rn

        if (tt + 1 < T) {                         // prefetch next wa/wb/nn
            const float4* wvn = (const float4*)(W_s + (tt + 1) * 16);
            wa = wvn[0];
            wb = wvn[1];
            nn = NN_s[tt + 1];
        }
    }

    atomicAdd(&out[b * C + ct], acc);
}

extern "C" void kernel_launch(void* const* d_in, const int* in_sizes, int n_in,
                              void* d_out, int out_size) {
    const int*   ids = (const int*)  d_in[0];
    const float* emb = (const float*)d_in[1];
    const float* ew  = (const float*)d_in[2];
    const float* nw  = (const float*)d_in[3];
    float* out = (float*)d_out;

    gnn_zero_out<<<BB, C>>>(out);   // d_out poisoned to 0xAA -> zero first

    dim3 grid(LL / T, BB);
    gnn_gather<<<grid, THREADS>>>(ids, ew, nw);
    gnn_kernel<<<grid, THREADS>>>(ids, emb, out);
}

// round 14
// speedup vs baseline: 1.0355x; 1.0355x over previous
#include <cuda_runtime.h>
#include <float.h>

#define VOCAB 8000
#define C 256
#define P 8
#define BB 16
#define LL 2048
#define T 32                  // positions per block tile
#define ROWS (T + 2*P)        // 48 window rows, all register-resident
#define THREADS 256

__device__ __forceinline__ void cp_async4(void* smem, const void* gptr) {
    unsigned s = (unsigned)__cvta_generic_to_shared(smem);
    asm volatile("cp.async.ca.shared.global [%0], [%1], 4;" :: "r"(s), "l"(gptr));
}

__global__ __launch_bounds__(THREADS, 3)
void gnn_kernel(const int* __restrict__ ids,
                const float* __restrict__ emb,
                const float* __restrict__ ew,
                const float* __restrict__ nw,
                float* __restrict__ out)
{
    __shared__ __align__(16) float W_s[T * 16];   // edge weights [pos][j]
    __shared__ __align__(16) float NN_s[T];       // node weights
    __shared__ int NX_s[ROWS];                    // window-row token ids

    const int b  = blockIdx.y;
    const int l0 = blockIdx.x * T;
    const int* idrow = ids + b * LL;
    const int tid = threadIdx.x;
    const int ct  = tid;                          // this thread's channel

    // ---- stage token ids ----
    if (tid < ROWS) {
        int p = l0 - P + tid;
        NX_s[tid] = (p >= 0 && p < LL) ? idrow[p] : 0;   // emb row 0 is all-zero
    }
    __syncthreads();

    // ---- gather group 0: positions 0..15 + node weights (cp.async, no reg wait)
    {
        int e = tid, t = e >> 4, j = e & 15;
        int k = j + (j >= P);                     // window slot, skipping center
        // nx==0 -> emb row 0 all-zero -> product 0 regardless of weight value
        cp_async4(&W_s[e], ew + (size_t)NX_s[t + P] * VOCAB + NX_s[t + k]);
    }
    if (tid < T)
        cp_async4(&NN_s[tid], nw + NX_s[tid + P]);
    asm volatile("cp.async.commit_group;" ::: "memory");

    // ---- gather group 1: positions 16..31 (covered by 16 compute iterations)
    {
        int e = tid + THREADS, t = e >> 4, j = e & 15;
        int k = j + (j >= P);
        cp_async4(&W_s[e], ew + (size_t)NX_s[t + P] * VOCAB + NX_s[t + k]);
    }
    asm volatile("cp.async.commit_group;" ::: "memory");

    // ---- full-register window: 48 rows, MLP=48 (covers gather group 0) ----
    float win[ROWS];
    #pragma unroll
    for (int r = 0; r < ROWS; r++)
        win[r] = emb[(size_t)NX_s[r] * C + ct];

    asm volatile("cp.async.wait_group 1;" ::: "memory");
    __syncthreads();

    float acc = 0.f;
    float4 wa = ((const float4*)W_s)[0];
    float4 wb = ((const float4*)W_s)[1];
    float nn  = NN_s[0];

    #pragma unroll
    for (int tt = 0; tt < T; tt++) {
        if (tt == 16) {                    // second gather half must be visible now
            asm volatile("cp.async.wait_group 0;" ::: "memory");
            __syncthreads();
            wa = ((const float4*)(W_s + 16 * 16))[0];
            wb = ((const float4*)(W_s + 16 * 16))[1];
            nn = NN_s[16];
        }

        // wc/wd loaded now, consumed >=16 instrs later (LDS latency hidden)
        const float4* wvt = (const float4*)(W_s + tt * 16);
        float4 wc = wvt[2], wd = wvt[3];

        float m0 = win[tt]     * wa.x;            // j=0
        float m1 = win[tt + 1] * wa.y;            // j=1
        #define STEP(j, wreg, m) m = fmaxf(m, win[tt + (j) + ((j) >= 8)] * (wreg));
        STEP(2,  wa.z, m0) STEP(3,  wa.w, m1)
        STEP(4,  wb.x, m0) STEP(5,  wb.y, m1) STEP(6,  wb.z, m0) STEP(7,  wb.w, m1)
        STEP(8,  wc.x, m0) STEP(9,  wc.y, m1) STEP(10, wc.z, m0) STEP(11, wc.w, m1)
        STEP(12, wd.x, m0) STEP(13, wd.y, m1) STEP(14, wd.z, m0) STEP(15, wd.w, m1)
        #undef STEP
        float m = fmaxf(m0, m1);

        float rn = win[tt + 8];
        acc += fmaf(nn, rn - m, m);               // (1-nn)*m + nn*rn

        // prefetch next iteration's wa/wb/nn (skip across the tt==16 barrier)
        if (tt + 1 < T && tt + 1 != 16) {
            const float4* wvn = (const float4*)(W_s + (tt + 1) * 16);
            wa = wvn[0];
            wb = wvn[1];
            nn = NN_s[tt + 1];
        }
    }

    atomicAdd(&out[b * C + ct], acc);
}

extern "C" void kernel_launch(void* const* d_in, const int* in_sizes, int n_in,
                              void* d_out, int out_size) {
    const int*   ids = (const int*)  d_in[0];
    const float* emb = (const float*)d_in[1];
    const float* ew  = (const float*)d_in[2];
    const float* nw  = (const float*)d_in[3];
    float* out = (float*)d_out;

    // graph memset node replaces the 3us zero kernel (d_out poisoned to 0xAA)
    cudaMemsetAsync(out, 0, (size_t)out_size * sizeof(float));

    dim3 grid(LL / T, BB);
    gnn_kernel<<<grid, THREADS>>>(ids, emb, ew, nw, out);
}

// round 15
// speedup vs baseline: 1.1353x; 1.0964x over previous
#include <cuda_runtime.h>
#include <float.h>

#define VOCAB 8000
#define C 256
#define P 8
#define BB 16
#define LL 2048
#define T 32                  // positions per block tile
#define ROWS (T + 2*P)        // 48 window-row token ids
#define THREADS 256
#define D 4                   // emb prefetch ring depth

__device__ __forceinline__ void cp_async4(void* smem, const void* gptr) {
    unsigned s = (unsigned)__cvta_generic_to_shared(smem);
    asm volatile("cp.async.ca.shared.global [%0], [%1], 4;" :: "r"(s), "l"(gptr));
}

__global__ __launch_bounds__(THREADS, 4)
void gnn_kernel(const int* __restrict__ ids,
                const float* __restrict__ emb,
                const float* __restrict__ ew,
                const float* __restrict__ nw,
                float* __restrict__ out)
{
    __shared__ __align__(16) float W_s[T * 16];   // edge weights [pos][j]
    __shared__ float NN_s[T];                     // node weights
    __shared__ int   NX_s[ROWS];                  // window-row token ids

    const int b  = blockIdx.y;
    const int l0 = blockIdx.x * T;
    const int* idrow = ids + b * LL;
    const int tid = threadIdx.x;
    const int ct  = tid;                          // this thread's channel

    // ---- stage token ids ----
    if (tid < ROWS) {
        int p = l0 - P + tid;
        NX_s[tid] = (p >= 0 && p < LL) ? idrow[p] : 0;   // emb row 0 is all-zero
    }
    __syncthreads();

    // ---- gather group 0: positions 0..15 + node weights (cp.async, no reg wait)
    {
        int e = tid, t = e >> 4, j = e & 15;
        int k = j + (j >= P);                     // window slot, skipping center
        // nx==0 -> emb row 0 all-zero -> product 0 regardless of weight value
        cp_async4(&W_s[e], ew + (size_t)NX_s[t + P] * VOCAB + NX_s[t + k]);
    }
    if (tid < T)
        cp_async4(&NN_s[tid], nw + NX_s[tid + P]);
    asm volatile("cp.async.commit_group;" ::: "memory");

    // ---- gather group 1: positions 16..31 (covered by 16 compute iterations)
    {
        int e = tid + THREADS, t = e >> 4, j = e & 15;
        int k = j + (j >= P);
        cp_async4(&W_s[e], ew + (size_t)NX_s[t + P] * VOCAB + NX_s[t + k]);
    }
    asm volatile("cp.async.commit_group;" ::: "memory");

    // ---- register window (17) + prefetch ring (D); overlaps gather group 0 ----
    float win[17];
    #pragma unroll
    for (int k = 0; k < 17; k++)
        win[k] = emb[(size_t)NX_s[k] * C + ct];
    float pf[D];
    #pragma unroll
    for (int d = 0; d < D; d++)
        pf[d] = emb[(size_t)NX_s[17 + d] * C + ct];

    // group 0 (+NN) landed while the 21 window LDGs were in flight
    asm volatile("cp.async.wait_group 1;" ::: "memory");
    __syncthreads();

    float acc = 0.f;
    float4 wa = ((const float4*)W_s)[0];
    float4 wb = ((const float4*)W_s)[1];
    float nn  = NN_s[0];

    #pragma unroll
    for (int tt = 0; tt < T; tt++) {
        if (tt == 16) {                    // second gather half must be visible now
            asm volatile("cp.async.wait_group 0;" ::: "memory");
            __syncthreads();
            wa = ((const float4*)(W_s + 16 * 16))[0];
            wb = ((const float4*)(W_s + 16 * 16))[1];
            nn = NN_s[16];
        }

        // emb prefetch: issued D+1 iters before first read
        int r = 17 + D + tt; if (r > ROWS - 1) r = ROWS - 1;   // clamped tail
        float newv = emb[(size_t)NX_s[r] * C + ct];

        // wc/wd loaded now, consumed >=20 instrs later (LDS latency hidden)
        const float4* wvt = (const float4*)(W_s + tt * 16);
        float4 wc = wvt[2], wd = wvt[3];

        float m0 = win[tt % 17]                 * wa.x;   // j=0 (no max needed)
        float m1 = win[(tt + 1) % 17]           * wa.y;   // j=1
        #define STEP(j, wreg, m) m = fmaxf(m, win[(tt + (j) + ((j) >= 8)) % 17] * (wreg));
        STEP(2,  wa.z, m0) STEP(3,  wa.w, m1)
        STEP(4,  wb.x, m0) STEP(5,  wb.y, m1) STEP(6,  wb.z, m0) STEP(7,  wb.w, m1)
        STEP(8,  wc.x, m0) STEP(9,  wc.y, m1) STEP(10, wc.z, m0) STEP(11, wc.w, m1)
        STEP(12, wd.x, m0) STEP(13, wd.y, m1) STEP(14, wd.z, m0) STEP(15, wd.w, m1)
        #undef STEP
        float m = fmaxf(m0, m1);

        float rn = win[(tt + 8) % 17];
        acc += fmaf(nn, rn - m, m);             // (1-nn)*m + nn*rn

        // prefetch next iteration's wa/wb/nn (skip across the tt==16 barrier)
        if (tt + 1 < T && tt + 1 != 16) {
            const float4* wvn = (const float4*)(W_s + (tt + 1) * 16);
            wa = wvn[0];
            wb = wvn[1];
            nn = NN_s[tt + 1];
        }

        // slide window through prefetch ring (fully unrolled -> register renaming)
        win[tt % 17] = pf[0];
        #pragma unroll
        for (int d = 0; d < D - 1; d++) pf[d] = pf[d + 1];
        pf[D - 1] = newv;
    }

    atomicAdd(&out[b * C + ct], acc);
}

extern "C" void kernel_launch(void* const* d_in, const int* in_sizes, int n_in,
                              void* d_out, int out_size) {
    const int*   ids = (const int*)  d_in[0];
    const float* emb = (const float*)d_in[1];
    const float* ew  = (const float*)d_in[2];
    const float* nw  = (const float*)d_in[3];
    float* out = (float*)d_out;

    // graph memset node replaces the 3us zero kernel (d_out poisoned to 0xAA)
    cudaMemsetAsync(out, 0, (size_t)out_size * sizeof(float));

    dim3 grid(LL / T, BB);
    gnn_kernel<<<grid, THREADS>>>(ids, emb, ew, nw, out);
}